// round 1
// baseline (speedup 1.0000x reference)
#include <cuda_runtime.h>
#include <math.h>

#define BATCH 64
#define NOBJ 16
#define NPRI 5460
#define NCLS 81
#define NCAND 49

__constant__ int c_split[7] = {0, 4096, 5120, 5376, 5440, 5456, 5460};

__device__ int    g_winner[BATCH * NPRI];
__device__ int    g_cls[BATCH * NPRI];
__device__ double g_conf;
__device__ double g_loc;
__device__ int    g_cnt;

// ---------------------------------------------------------------------------
// Kernel 0: init accumulators + winner array
// ---------------------------------------------------------------------------
__global__ void init_kernel() {
    int i = blockIdx.x * blockDim.x + threadIdx.x;
    if (i == 0) { g_conf = 0.0; g_loc = 0.0; g_cnt = 0; }
    if (i < BATCH * NPRI) g_winner[i] = -1;
}

// ---------------------------------------------------------------------------
// Kernel 1: ATSS assignment. One block per (image, object).
//   - distances to all priors per level, iterative argmin top-k (tie -> lower idx)
//   - IoU of box vs selected candidate priors (pov)
//   - threshold = mean + std(ddof=1) over 49 pov values
//   - pos = (pov > thresh) && center-inside-box
//   - pos: atomicMax winner, accumulate DIoU loss + count
// ---------------------------------------------------------------------------
__global__ void assign_kernel(const float* __restrict__ locs,
                              const float* __restrict__ boxes,
                              const float* __restrict__ priors) {
    __shared__ float sh_dist[4096];
    __shared__ float s_wv[4];
    __shared__ int   s_wi[4];
    __shared__ int   s_cand[NCAND];
    __shared__ float s_pov[NCAND];
    __shared__ float s_thresh;
    __shared__ float s_loc;
    __shared__ int   s_cnt;

    const int b   = blockIdx.x;
    const int o   = blockIdx.y;
    const int tid = threadIdx.x;
    const int lane = tid & 31;
    const int wid  = tid >> 5;

    const float* bx = boxes + (b * NOBJ + o) * 4;
    const float bx1 = bx[0], by1 = bx[1], bx2 = bx[2], by2 = bx[3];
    const float bcx = (bx1 + bx2) * 0.5f;
    const float bcy = (by1 + by2) * 0.5f;
    const float area_a = (bx2 - bx1) * (by2 - by1);

    if (tid == 0) { s_loc = 0.0f; s_cnt = 0; }

    int slot = 0;
    for (int l = 0; l < 6; l++) {
        const int base = c_split[l];
        const int L    = c_split[l + 1] - base;

        // fill distances
        for (int p = tid; p < L; p += blockDim.x) {
            float pcx = priors[(base + p) * 4 + 0];
            float pcy = priors[(base + p) * 4 + 1];
            float dx = bcx - pcx, dy = bcy - pcy;
            sh_dist[p] = sqrtf(dx * dx + dy * dy);
        }
        __syncthreads();

        const int k = (L < 9) ? L : 9;
        for (int t = 0; t < k; t++, slot++) {
            // per-thread strided argmin (keeps lowest index on exact ties)
            float bv = INFINITY;
            int   bi = 0x7fffffff;
            for (int p = tid; p < L; p += blockDim.x) {
                float v = sh_dist[p];
                if (v < bv) { bv = v; bi = p; }
            }
            // warp reduce (min value, tie -> lower index)
            for (int off = 16; off; off >>= 1) {
                float v2 = __shfl_down_sync(0xffffffffu, bv, off);
                int   i2 = __shfl_down_sync(0xffffffffu, bi, off);
                if (v2 < bv || (v2 == bv && i2 < bi)) { bv = v2; bi = i2; }
            }
            if (lane == 0) { s_wv[wid] = bv; s_wi[wid] = bi; }
            __syncthreads();
            if (tid == 0) {
                float best = s_wv[0]; int besti = s_wi[0];
                for (int w = 1; w < 4; w++) {
                    if (s_wv[w] < best || (s_wv[w] == best && s_wi[w] < besti)) {
                        best = s_wv[w]; besti = s_wi[w];
                    }
                }
                sh_dist[besti] = INFINITY;
                const int g = base + besti;
                const float pcx = priors[g * 4 + 0];
                const float pcy = priors[g * 4 + 1];
                const float pw  = priors[g * 4 + 2];
                const float ph  = priors[g * 4 + 3];
                const float px1 = pcx - pw * 0.5f, py1 = pcy - ph * 0.5f;
                const float px2 = pcx + pw * 0.5f, py2 = pcy + ph * 0.5f;
                const float tlx = fmaxf(bx1, px1), tly = fmaxf(by1, py1);
                const float brx = fminf(bx2, px2), bry = fminf(by2, py2);
                const float inter = fmaxf(brx - tlx, 0.0f) * fmaxf(bry - tly, 0.0f);
                const float area_b = (px2 - px1) * (py2 - py1);
                s_cand[slot] = g;
                s_pov[slot]  = inter / (area_a + area_b - inter + 1e-10f);
            }
            __syncthreads();
        }
    }

    // threshold = mean + std(ddof=1) over 49 values
    if (tid == 0) {
        float sum = 0.0f;
        for (int j = 0; j < NCAND; j++) sum += s_pov[j];
        const float mean = sum / 49.0f;
        float ss = 0.0f;
        for (int j = 0; j < NCAND; j++) { float d = s_pov[j] - mean; ss += d * d; }
        s_thresh = mean + sqrtf(ss / 48.0f);
    }
    __syncthreads();

    // per-candidate positivity + DIoU
    if (tid < NCAND) {
        const int g = s_cand[tid];
        const float pcx = priors[g * 4 + 0];
        const float pcy = priors[g * 4 + 1];
        const float pw  = priors[g * 4 + 2];
        const float ph  = priors[g * 4 + 3];
        const bool inside = (bx1 <= pcx) && (pcx <= bx2) && (by1 <= pcy) && (pcy <= by2);
        if (inside && (s_pov[tid] > s_thresh)) {
            atomicMax(&g_winner[b * NPRI + g], o);
            const float* gp = locs + ((size_t)b * NPRI + g) * 4;
            const float g0 = gp[0], g1 = gp[1], g2 = gp[2], g3 = gp[3];
            // decode
            const float dcx = (g0 * pw) / 10.0f + pcx;
            const float dcy = (g1 * ph) / 10.0f + pcy;
            const float dw  = expf(g2 / 5.0f) * pw;
            const float dh  = expf(g3 / 5.0f) * ph;
            const float px1 = dcx - dw * 0.5f, py1 = dcy - dh * 0.5f;
            const float px2 = dcx + dw * 0.5f, py2 = dcy + dh * 0.5f;
            // DIoU
            const float tlx = fmaxf(px1, bx1), tly = fmaxf(py1, by1);
            const float brx = fminf(px2, bx2), bry = fminf(py2, by2);
            const float inter = fmaxf(brx - tlx, 0.0f) * fmaxf(bry - tly, 0.0f);
            const float ap = fmaxf(px2 - px1, 0.0f) * fmaxf(py2 - py1, 0.0f);
            const float iou = inter / (ap + area_a - inter + 1e-7f);
            const float cpx = (px1 + px2) * 0.5f, cpy = (py1 + py2) * 0.5f;
            const float ddx = cpx - bcx, ddy = cpy - bcy;
            const float d2 = ddx * ddx + ddy * ddy;
            const float etlx = fminf(px1, bx1), etly = fminf(py1, by1);
            const float ebrx = fmaxf(px2, bx2), ebry = fmaxf(py2, by2);
            const float ex = ebrx - etlx, ey = ebry - etly;
            const float diag2 = ex * ex + ey * ey + 1e-7f;
            const float loss = 1.0f - iou + d2 / diag2;
            atomicAdd(&s_loc, loss);
            atomicAdd(&s_cnt, 1);
        }
    }
    __syncthreads();
    if (tid == 0 && s_cnt > 0) {
        atomicAdd(&g_loc, (double)s_loc);
        atomicAdd(&g_cnt, s_cnt);
    }
}

// ---------------------------------------------------------------------------
// Kernel 2: resolve per-prior class labels from winner array
// ---------------------------------------------------------------------------
__global__ void cls_kernel(const int* __restrict__ labels) {
    int i = blockIdx.x * blockDim.x + threadIdx.x;
    if (i < BATCH * NPRI) {
        int w = g_winner[i];
        g_cls[i] = (w >= 0) ? labels[(i / NPRI) * NOBJ + w] : 0;
    }
}

// ---------------------------------------------------------------------------
// Kernel 3: focal loss over all scores (HBM-bound). float4 grid-stride.
// ---------------------------------------------------------------------------
__global__ void focal_kernel(const float* __restrict__ scores) {
    const int total = BATCH * NPRI * NCLS;  // 28,304,640 (divisible by 4)
    float sum = 0.0f;
    const int stride = gridDim.x * blockDim.x * 4;
    for (int i = (blockIdx.x * blockDim.x + threadIdx.x) * 4; i < total; i += stride) {
        const float4 s = *reinterpret_cast<const float4*>(scores + i);
        const float v[4] = {s.x, s.y, s.z, s.w};
#pragma unroll
        for (int j = 0; j < 4; j++) {
            const int e   = i + j;
            const int row = e / NCLS;
            const int c   = e - row * NCLS;
            const int cls = g_cls[row];
            const float x = v[j];
            const float t = expf(-fabsf(x));
            const float lse = log1pf(t);               // log(1 + exp(-|x|))
            const float p = (x >= 0.0f) ? 1.0f / (1.0f + t) : t / (1.0f + t);
            float val;
            if (c == cls) {
                const float om = 1.0f - p;
                val = 0.25f * om * om * (lse - fminf(x, 0.0f));   // -logsig(x)
            } else {
                val = 0.75f * p * p * (lse - fminf(-x, 0.0f));    // -logsig(-x)
            }
            sum += val;
        }
    }
    // block reduction
    for (int off = 16; off; off >>= 1) sum += __shfl_down_sync(0xffffffffu, sum, off);
    __shared__ float ws[32];
    const int lane = threadIdx.x & 31;
    const int wid  = threadIdx.x >> 5;
    if (lane == 0) ws[wid] = sum;
    __syncthreads();
    if (wid == 0) {
        sum = (lane < (blockDim.x >> 5)) ? ws[lane] : 0.0f;
        for (int off = 16; off; off >>= 1) sum += __shfl_down_sync(0xffffffffu, sum, off);
        if (lane == 0) atomicAdd(&g_conf, (double)sum);
    }
}

// ---------------------------------------------------------------------------
// Kernel 4: finalize scalar
// ---------------------------------------------------------------------------
__global__ void finalize_kernel(float* out) {
    const double conf = g_conf / (double)(BATCH * NPRI);
    const double loc  = g_loc / fmax((double)g_cnt, 1.0);
    out[0] = (float)(conf + loc);
}

// ---------------------------------------------------------------------------
extern "C" void kernel_launch(void* const* d_in, const int* in_sizes, int n_in,
                              void* d_out, int out_size) {
    const float* locs   = (const float*)d_in[0];
    const float* scores = (const float*)d_in[1];
    const float* boxes  = (const float*)d_in[2];
    const int*   labels = (const int*)d_in[3];
    const float* priors = (const float*)d_in[4];

    init_kernel<<<(BATCH * NPRI + 255) / 256, 256>>>();
    assign_kernel<<<dim3(BATCH, NOBJ), 128>>>(locs, boxes, priors);
    cls_kernel<<<(BATCH * NPRI + 255) / 256, 256>>>(labels);
    focal_kernel<<<2960, 256>>>(scores);
    finalize_kernel<<<1, 1>>>((float*)d_out);
}